// round 15
// baseline (speedup 1.0000x reference)
#include <cuda_runtime.h>
#include <cuda_fp16.h>
#include <cstdint>
#include <math.h>

// ---------------- problem constants ----------------
#define Cc   192
#define HW   65536           // 256*256
#define NPIX 131072          // B*H*W
#define DWIN 3072            // 16*C
#define NWIN 8192            // B*(H/4)*(W/4)
#define DH   768             // 4*C

// ---------------- scratch (device globals: allocation-free) ----------------
__device__ __half g_wf [(size_t)DWIN * DWIN];      // 18.9 MB  ([K][N] row-major)
__device__ __half g_Xw [(size_t)NWIN * DWIN];      // 50.3 MB
__device__ __half g_Z  [(size_t)NPIX * Cc];        // 50.3 MB
__device__ __half g_X2 [(size_t)NPIX * Cc];        // 50.3 MB (residual chain: fp16)
__device__ __half g_U  [(size_t)NPIX * DH];        // 201.3 MB
__device__ __half g_projH[Cc * Cc];
__device__ __half g_fc1H [Cc * DH];
__device__ __half g_fc2H [DH * Cc];

// ---------------- helpers ----------------
__device__ __forceinline__ float gelu_exact(float x) {
    return 0.5f * x * (1.0f + erff(x * 0.70710678118654752f));
}
__device__ __forceinline__ uint32_t smem_u32(const void* p) {
    uint32_t a;
    asm("{ .reg .u64 t; cvta.to.shared.u64 t, %1; cvt.u32.u64 %0, t; }" : "=r"(a) : "l"(p));
    return a;
}

__device__ __forceinline__ int cd_sign16(int i, int j) {
    int s = 1;
    for (int n = 16; n > 1;) {
        int h = n >> 1;
        if (i < h && j < h) {
        } else if (i < h) {
            int t = j - h; j = i; i = t;
        } else if (j < h) {
            if (j != 0) s = -s;
            i = i - h;
        } else {
            int ip = i - h, jp = j - h;
            if (jp == 0) s = -s;
            i = jp; j = ip;
        }
        n = h;
    }
    return s;
}

// ---------------- merged prep kernel -------------------------------------
#define WF_E4    (DWIN * (DWIN / 4))
#define WF_BLK   (WF_E4 / 256)
#define CV_PROJ4 (Cc * Cc / 4)
#define CV_FC14  (Cc * DH / 4)
#define CV_FC24  (DH * Cc / 4)
#define CV_TOT4  (CV_PROJ4 + CV_FC14 + CV_FC24)
#define CV_BLK   ((CV_TOT4 + 255) / 256)

__global__ void prep_kernel(const float* __restrict__ w_sed, __half* __restrict__ wf,
                            const float* __restrict__ proj_w, __half* __restrict__ projH,
                            const float* __restrict__ fc1_w,  __half* __restrict__ fc1H,
                            const float* __restrict__ fc2_w,  __half* __restrict__ fc2H) {
    int blk = blockIdx.x;
    if (blk < WF_BLK) {
        int e4 = blk * 256 + threadIdx.x;
        int row  = e4 / (DWIN / 4);
        int col4 = (e4 % (DWIN / 4)) * 4;
        int i = row / Cc, a = row % Cc;
        int k = col4 / Cc, b = col4 % Cc;
        int j = i ^ k;
        float s = (float)cd_sign16(i, j);
        float4 v = *(const float4*)(w_sed + ((size_t)j * Cc + a) * Cc + b);
        __half2* d = (__half2*)(wf + (size_t)row * DWIN + col4);
        d[0] = __floats2half2_rn(s * v.x, s * v.y);
        d[1] = __floats2half2_rn(s * v.z, s * v.w);
    } else {
        int e4 = (blk - WF_BLK) * 256 + threadIdx.x;
        const float* src; __half* dst;
        if (e4 < CV_PROJ4) {
            src = proj_w + e4 * 4; dst = projH + e4 * 4;
        } else if (e4 < CV_PROJ4 + CV_FC14) {
            int o = (e4 - CV_PROJ4) * 4; src = fc1_w + o; dst = fc1H + o;
        } else if (e4 < CV_TOT4) {
            int o = (e4 - CV_PROJ4 - CV_FC14) * 4; src = fc2_w + o; dst = fc2H + o;
        } else return;
        float4 v = *(const float4*)src;
        __half2* d = (__half2*)dst;
        d[0] = __floats2half2_rn(v.x, v.y);
        d[1] = __floats2half2_rn(v.z, v.w);
    }
}

// ---------------- kernel: LN1 via smem transpose (coalesced x reads) -------
#define LN1_SMEM (192 * 68 * 4)   // 52224 bytes

__global__ __launch_bounds__(128)
void ln1_window_kernel(const float* __restrict__ x,
                       const float* __restrict__ g,
                       const float* __restrict__ be,
                       __half* __restrict__ Xw) {
    extern __shared__ float s[];   // [192][68]
    int t  = threadIdx.x;
    int n0 = blockIdx.x * 64;
    int b  = n0 >> 16;
    int hw0 = n0 & (HW - 1);
    const float* xb = x + (size_t)b * Cc * HW + hw0;
#pragma unroll
    for (int j = 0; j < 24; j++) {
        int idx = t + j * 128;
        int c = idx >> 4, q = idx & 15;
        float4 v = *(const float4*)(xb + (size_t)c * HW + q * 4);
        float* d = &s[c * 68 + q * 4];
        d[0] = v.x; d[1] = v.y; d[2] = v.z; d[3] = v.w;
    }
    __syncthreads();
    if (t < 64) {
        int n  = n0 + t;
        int hw = n & (HW - 1);
        int h  = hw >> 8, w = hw & 255;
        float sum = 0.f, sum2 = 0.f;
#pragma unroll 4
        for (int c = 0; c < Cc; c++) {
            float v = s[c * 68 + t];
            sum += v; sum2 += v * v;
        }
        float m  = sum * (1.0f / Cc);
        float rs = rsqrtf(sum2 * (1.0f / Cc) - m * m + 1e-5f);
        int r = (b << 12) + ((h >> 2) << 6) + (w >> 2);
        int p = ((h & 3) << 2) + (w & 3);
        __half* dst = Xw + (size_t)r * DWIN + p * Cc;
#pragma unroll
        for (int c8 = 0; c8 < Cc; c8 += 8) {
            __half2 h4[4];
#pragma unroll
            for (int u = 0; u < 4; u++) {
                int c = c8 + u * 2;
                float v0 = (s[(c + 0) * 68 + t] - m) * rs * g[c + 0] + be[c + 0];
                float v1 = (s[(c + 1) * 68 + t] - m) * rs * g[c + 1] + be[c + 1];
                h4[u] = __floats2half2_rn(v0, v1);
            }
            *(uint4*)(dst + c8) = *(uint4*)h4;
        }
    }
}

// ---------------- common HMMA --------------------------------------------
__device__ __forceinline__ void hmma(float* c, const uint32_t* a, const uint32_t* b) {
    asm volatile(
        "mma.sync.aligned.m16n8k16.row.col.f32.f16.f16.f32 "
        "{%0,%1,%2,%3}, {%4,%5,%6,%7}, {%8,%9}, {%0,%1,%2,%3};"
        : "+f"(c[0]), "+f"(c[1]), "+f"(c[2]), "+f"(c[3])
        : "r"(a[0]), "r"(a[1]), "r"(a[2]), "r"(a[3]), "r"(b[0]), "r"(b[1]));
}

// ============================================================================
// fc1 + LN2 fused: A = LN(X2) computed in-smem (K=192 fully resident).
// grid (6, NPIX/128). U(fp16) = gelu(LN(X2) @ fc1 + bias).
// smem: [0,1536) g,b fp32; [2048, +49152) A (3 k-tiles); then B (3 k-tiles).
// ============================================================================
#define FC1_SMEM (2048 + 49152 + 49152)   // 100352

__global__ __launch_bounds__(256, 2)
void fc1_ln_fused(const __half* __restrict__ X2, const __half* __restrict__ Bw,
                  __half* __restrict__ U,
                  const float* __restrict__ g, const float* __restrict__ be,
                  const float* __restrict__ bias) {
    extern __shared__ char smem[];
    uint32_t sb  = smem_u32(smem);
    float* sGB   = (float*)smem;            // [192] g, [192] b
    uint32_t sA0 = sb + 2048;
    uint32_t sB0 = sA0 + 49152;

    int tid  = threadIdx.x;
    int wid  = tid >> 5, lane = tid & 31;
    int wm   = wid & 3;
    int wn   = wid >> 2;
    int row0 = blockIdx.y * 128;
    int col0 = blockIdx.x * 128;
    int lg   = lane >> 2;
    int lt   = lane & 3;

    // stage gamma/beta
    if (tid < 192) { sGB[tid] = g[tid]; sGB[192 + tid] = be[tid]; }

    // async-load all 3 A k-tiles (raw X2) and 3 B k-tiles
#pragma unroll
    for (int t3 = 0; t3 < 3; t3++) {
#pragma unroll
        for (int i = 0; i < 4; i++) {
            int idx = tid + i * 256;
            int m = idx >> 3, c = idx & 7;
            const __half* src = X2 + (size_t)(row0 + m) * Cc + t3 * 64 + (c << 3);
            uint32_t dst = sA0 + t3 * 16384 + m * 128 + ((c ^ (m & 7)) << 4);
            asm volatile("cp.async.cg.shared.global [%0], [%1], 16;"
                         :: "r"(dst), "l"(src) : "memory");
        }
#pragma unroll
        for (int i = 0; i < 4; i++) {
            int idx = tid + i * 256;
            int k = idx >> 4, c = idx & 15;
            const __half* src = Bw + (size_t)(t3 * 64 + k) * DH + col0 + (c << 3);
            uint32_t dst = sB0 + t3 * 16384 + k * 256 + (((c & 8) | ((c & 7) ^ (k & 7))) << 4);
            asm volatile("cp.async.cg.shared.global [%0], [%1], 16;"
                         :: "r"(dst), "l"(src) : "memory");
        }
    }
    asm volatile("cp.async.commit_group;" ::: "memory");
    asm volatile("cp.async.wait_group 0;" ::: "memory");
    __syncthreads();

    // LN2 in-smem: threads 0..127 each own one row (two passes)
    if (tid < 128) {
        int r = tid;
        float sum = 0.f, sum2 = 0.f;
#pragma unroll
        for (int t3 = 0; t3 < 3; t3++) {
            uint32_t base = sA0 + t3 * 16384 + r * 128;
#pragma unroll
            for (int c = 0; c < 8; c++) {
                uint32_t a0, a1, a2, a3;
                asm volatile("ld.shared.v4.b32 {%0,%1,%2,%3}, [%4];"
                             : "=r"(a0), "=r"(a1), "=r"(a2), "=r"(a3)
                             : "r"(base + ((c ^ (r & 7)) << 4)));
                uint32_t w4[4] = {a0, a1, a2, a3};
#pragma unroll
                for (int u = 0; u < 4; u++) {
                    float2 f = __half22float2(*(__half2*)&w4[u]);
                    sum += f.x + f.y; sum2 += f.x * f.x + f.y * f.y;
                }
            }
        }
        float m  = sum * (1.0f / Cc);
        float rs = rsqrtf(sum2 * (1.0f / Cc) - m * m + 1e-5f);
#pragma unroll
        for (int t3 = 0; t3 < 3; t3++) {
            uint32_t base = sA0 + t3 * 16384 + r * 128;
#pragma unroll
            for (int c = 0; c < 8; c++) {
                uint32_t addr = base + ((c ^ (r & 7)) << 4);
                uint32_t a0, a1, a2, a3;
                asm volatile("ld.shared.v4.b32 {%0,%1,%2,%3}, [%4];"
                             : "=r"(a0), "=r"(a1), "=r"(a2), "=r"(a3) : "r"(addr));
                uint32_t w4[4] = {a0, a1, a2, a3};
                int cbase = t3 * 64 + c * 8;
#pragma unroll
                for (int u = 0; u < 4; u++) {
                    float2 f = __half22float2(*(__half2*)&w4[u]);
                    int cc = cbase + u * 2;
                    float v0 = (f.x - m) * rs * sGB[cc]     + sGB[192 + cc];
                    float v1 = (f.y - m) * rs * sGB[cc + 1] + sGB[192 + cc + 1];
                    __half2 hv = __floats2half2_rn(v0, v1);
                    w4[u] = *(uint32_t*)&hv;
                }
                asm volatile("st.shared.v4.b32 [%0], {%1,%2,%3,%4};"
                             :: "r"(addr), "r"(w4[0]), "r"(w4[1]), "r"(w4[2]), "r"(w4[3])
                             : "memory");
            }
        }
    }
    __syncthreads();

    // MMA mainloop: 3 resident k-tiles
    float cacc[2][8][4];
#pragma unroll
    for (int mt = 0; mt < 2; mt++)
#pragma unroll
        for (int nt = 0; nt < 8; nt++)
#pragma unroll
            for (int q = 0; q < 4; q++) cacc[mt][nt][q] = 0.f;

#pragma unroll
    for (int kt = 0; kt < 3; kt++) {
        uint32_t sA = sA0 + kt * 16384;
        uint32_t sB = sB0 + kt * 16384;
#pragma unroll
        for (int ks = 0; ks < 4; ks++) {
            uint32_t af[2][4], bf[8][2];
#pragma unroll
            for (int mt = 0; mt < 2; mt++) {
                int m = wm * 32 + mt * 16 + (lane & 15);
                int c = ks * 2 + (lane >> 4);
                uint32_t addr = sA + m * 128 + ((c ^ (m & 7)) << 4);
                asm volatile("ldmatrix.sync.aligned.m8n8.x4.shared.b16 {%0,%1,%2,%3}, [%4];"
                             : "=r"(af[mt][0]), "=r"(af[mt][1]), "=r"(af[mt][2]), "=r"(af[mt][3])
                             : "r"(addr));
            }
#pragma unroll
            for (int np = 0; np < 4; np++) {
                int k  = ks * 16 + (lane & 15);
                int cn = wn * 8 + np * 2 + (lane >> 4);
                uint32_t addr = sB + k * 256 + (((cn & 8) | ((cn & 7) ^ (k & 7))) << 4);
                asm volatile("ldmatrix.sync.aligned.m8n8.x4.trans.shared.b16 {%0,%1,%2,%3}, [%4];"
                             : "=r"(bf[np * 2][0]), "=r"(bf[np * 2][1]),
                               "=r"(bf[np * 2 + 1][0]), "=r"(bf[np * 2 + 1][1])
                             : "r"(addr));
            }
#pragma unroll
            for (int mt = 0; mt < 2; mt++)
#pragma unroll
                for (int nt = 0; nt < 8; nt++)
                    hmma(cacc[mt][nt], af[mt], bf[nt]);
        }
    }

    // epilogue: U = gelu(D + bias)
#pragma unroll
    for (int mt = 0; mt < 2; mt++) {
#pragma unroll
        for (int nt = 0; nt < 8; nt++) {
            int r = row0 + wm * 32 + mt * 16 + lg;
            int c = col0 + wn * 64 + nt * 8 + lt * 2;
#pragma unroll
            for (int half = 0; half < 2; half++) {
                int rr = r + half * 8;
                float v0 = cacc[mt][nt][half * 2 + 0];
                float v1 = cacc[mt][nt][half * 2 + 1];
                *(__half2*)(U + (size_t)rr * DH + c) =
                    __floats2half2_rn(gelu_exact(v0 + bias[c]),
                                      gelu_exact(v1 + bias[c + 1]));
            }
        }
    }
}

// ---------------- fp16 mma.sync GEMM, 3-stage cp.async, 2 CTAs/SM -----------
// MODE 1: X2(fp16) = D + bias + res_bchw(fp32)        (proj + residual)
// MODE 3: out_bchw(fp32) = res_rowmaj(fp16) + D + b   (fc2, transposed store)
// MODE 4: Z(fp16)  = gelu(D), reverse-window scatter  (GEMM1 fused)
#define STG 32768

template <int MODE, int NT>
__global__ __launch_bounds__(256, 2)
void hgemm(const __half* __restrict__ A, const __half* __restrict__ Bm,
           void* __restrict__ Cv, int M, int N, int K,
           const float* __restrict__ bias, const void* __restrict__ res) {
    extern __shared__ char smem[];
    uint32_t sb = smem_u32(smem);

    int tid  = threadIdx.x;
    int wid  = tid >> 5, lane = tid & 31;
    int wm   = wid & 3;
    int wn   = wid >> 2;
    int row0 = blockIdx.y * 128;
    int col0 = blockIdx.x * (NT * 16);
    int lg   = lane >> 2;
    int lt   = lane & 3;

    float cacc[2][NT][4];
#pragma unroll
    for (int mt = 0; mt < 2; mt++)
#pragma unroll
        for (int nt = 0; nt < NT; nt++)
#pragma unroll
            for (int q = 0; q < 4; q++) cacc[mt][nt][q] = 0.f;

    int nk = K >> 6;

    auto load_stage = [&](int kt, int buf) {
        uint32_t sA = sb + buf * STG;
        uint32_t sB = sA + 16384;
#pragma unroll
        for (int i = 0; i < 4; i++) {
            int idx = tid + i * 256;
            int m = idx >> 3, c = idx & 7;
            const __half* src = A + (size_t)(row0 + m) * K + (kt << 6) + (c << 3);
            uint32_t dst = sA + m * 128 + ((c ^ (m & 7)) << 4);
            asm volatile("cp.async.cg.shared.global [%0], [%1], 16;"
                         :: "r"(dst), "l"(src) : "memory");
        }
#pragma unroll
        for (int i = 0; i < NT / 2; i++) {
            int idx = tid + i * 256;
            int k = idx / (2 * NT), c = idx % (2 * NT);
            int n = col0 + (c << 3);
            const __half* src = Bm + (size_t)((kt << 6) + k) * N + (n < N ? n : 0);
            uint32_t dst = sB + k * 256 + (((c & 8) | ((c & 7) ^ (k & 7))) << 4);
            int ssz = (n < N) ? 16 : 0;
            asm volatile("cp.async.cg.shared.global [%0], [%1], 16, %2;"
                         :: "r"(dst), "l"(src), "r"(ssz) : "memory");
        }
        asm volatile("cp.async.commit_group;" ::: "memory");
    };

    uint32_t af[2][2][4], bf[2][NT][2];
    auto load_frags = [&](uint32_t sA, uint32_t sB, int ks, int pb) {
#pragma unroll
        for (int mt = 0; mt < 2; mt++) {
            int m = wm * 32 + mt * 16 + (lane & 15);
            int c = ks * 2 + (lane >> 4);
            uint32_t addr = sA + m * 128 + ((c ^ (m & 7)) << 4);
            asm volatile("ldmatrix.sync.aligned.m8n8.x4.shared.b16 {%0,%1,%2,%3}, [%4];"
                         : "=r"(af[pb][mt][0]), "=r"(af[pb][mt][1]),
                           "=r"(af[pb][mt][2]), "=r"(af[pb][mt][3])
                         : "r"(addr));
        }
#pragma unroll
        for (int np = 0; np < NT / 2; np++) {
            int k  = ks * 16 + (lane & 15);
            int cn = wn * NT + np * 2 + (lane >> 4);
            uint32_t addr = sB + k * 256 + (((cn & 8) | ((cn & 7) ^ (k & 7))) << 4);
            asm volatile("ldmatrix.sync.aligned.m8n8.x4.trans.shared.b16 {%0,%1,%2,%3}, [%4];"
                         : "=r"(bf[pb][np * 2][0]), "=r"(bf[pb][np * 2][1]),
                           "=r"(bf[pb][np * 2 + 1][0]), "=r"(bf[pb][np * 2 + 1][1])
                         : "r"(addr));
        }
    };

    load_stage(0, 0);
    if (nk > 1) load_stage(1, 1);

    for (int kt = 0; kt < nk; kt++) {
        int buf = kt % 3;
        if (kt + 1 < nk) {
            asm volatile("cp.async.wait_group 1;" ::: "memory");
        } else {
            asm volatile("cp.async.wait_group 0;" ::: "memory");
        }
        __syncthreads();
        if (kt + 2 < nk) load_stage(kt + 2, (kt + 2) % 3);

        uint32_t sA = sb + buf * STG;
        uint32_t sB = sA + 16384;

        load_frags(sA, sB, 0, 0);
#pragma unroll
        for (int ks = 0; ks < 4; ks++) {
            int cur = ks & 1;
            if (ks < 3) load_frags(sA, sB, ks + 1, cur ^ 1);
#pragma unroll
            for (int mt = 0; mt < 2; mt++)
#pragma unroll
                for (int nt = 0; nt < NT; nt++)
                    hmma(cacc[mt][nt], af[cur][mt], bf[cur][nt]);
        }
    }
    __syncthreads();

    // ---------------- epilogue ----------------
#pragma unroll
    for (int mt = 0; mt < 2; mt++) {
#pragma unroll
        for (int nt = 0; nt < NT; nt++) {
            int r = row0 + wm * 32 + mt * 16 + lg;
            int c = col0 + wn * (NT * 8) + nt * 8 + lt * 2;
            if (c >= N) continue;
#pragma unroll
            for (int half = 0; half < 2; half++) {
                int rr = r + half * 8;
                float v0 = cacc[mt][nt][half * 2 + 0];
                float v1 = cacc[mt][nt][half * 2 + 1];
                if (MODE == 1) {
                    int rb = rr >> 16, rhw = rr & (HW - 1);
                    const float* rp = (const float*)res + (size_t)rb * Cc * HW + rhw;
                    float o0 = v0 + bias[c]     + rp[(size_t)c * HW];
                    float o1 = v1 + bias[c + 1] + rp[(size_t)(c + 1) * HW];
                    *(__half2*)((__half*)Cv + (size_t)rr * N + c) = __floats2half2_rn(o0, o1);
                } else if (MODE == 3) {
                    int rb = rr >> 16, rhw = rr & (HW - 1);
                    const __half* rp = (const __half*)res + (size_t)rr * Cc;
                    float* op = (float*)Cv + (size_t)rb * Cc * HW + rhw;
                    float2 rf = __half22float2(*(const __half2*)(rp + c));
                    op[(size_t)c * HW]       = rf.x + v0 + bias[c];
                    op[(size_t)(c + 1) * HW] = rf.y + v1 + bias[c + 1];
                } else {  // MODE 4
                    int p  = c / Cc;
                    int cc = c - p * Cc;
                    int bb = rr >> 12;
                    int hq = (rr >> 6) & 63, wq = rr & 63;
                    int h = (hq << 2) + (p >> 2), w = (wq << 2) + (p & 3);
                    int n = (bb << 16) + (h << 8) + w;
                    *(__half2*)((__half*)Cv + (size_t)n * Cc + cc) =
                        __floats2half2_rn(gelu_exact(v0), gelu_exact(v1));
                }
            }
        }
    }
}

// ---------------- launch ----------------
extern "C" void kernel_launch(void* const* d_in, const int* in_sizes, int n_in,
                              void* d_out, int out_size) {
    const float* x       = (const float*)d_in[0];
    const float* norm1_g = (const float*)d_in[1];
    const float* norm1_b = (const float*)d_in[2];
    const float* w_sed   = (const float*)d_in[3];
    const float* proj_w  = (const float*)d_in[4];
    const float* proj_b  = (const float*)d_in[5];
    const float* norm2_g = (const float*)d_in[6];
    const float* norm2_b = (const float*)d_in[7];
    const float* fc1_w   = (const float*)d_in[8];
    const float* fc1_b   = (const float*)d_in[9];
    const float* fc2_w   = (const float*)d_in[10];
    const float* fc2_b   = (const float*)d_in[11];
    float* out = (float*)d_out;

    __half *wf, *Xw, *Z, *X2, *U, *projH, *fc1H, *fc2H;
    cudaGetSymbolAddress((void**)&wf,    g_wf);
    cudaGetSymbolAddress((void**)&Xw,    g_Xw);
    cudaGetSymbolAddress((void**)&Z,     g_Z);
    cudaGetSymbolAddress((void**)&X2,    g_X2);
    cudaGetSymbolAddress((void**)&U,     g_U);
    cudaGetSymbolAddress((void**)&projH, g_projH);
    cudaGetSymbolAddress((void**)&fc1H,  g_fc1H);
    cudaGetSymbolAddress((void**)&fc2H,  g_fc2H);

    const int SMEM = 3 * STG;  // 98304
    cudaFuncSetAttribute((hgemm<1, 6>), cudaFuncAttributeMaxDynamicSharedMemorySize, SMEM);
    cudaFuncSetAttribute((hgemm<3, 6>), cudaFuncAttributeMaxDynamicSharedMemorySize, SMEM);
    cudaFuncSetAttribute((hgemm<4, 8>), cudaFuncAttributeMaxDynamicSharedMemorySize, SMEM);
    cudaFuncSetAttribute(fc1_ln_fused, cudaFuncAttributeMaxDynamicSharedMemorySize, FC1_SMEM);
    cudaFuncSetAttribute(ln1_window_kernel, cudaFuncAttributeMaxDynamicSharedMemorySize, LN1_SMEM);

    // 0. merged prep: wf build + all weight fp16 conversions (one launch)
    prep_kernel<<<WF_BLK + CV_BLK, 256>>>(w_sed, wf, proj_w, projH,
                                          fc1_w, fc1H, fc2_w, fc2H);

    // 1. LN1 + window partition via smem transpose (coalesced x reads)
    ln1_window_kernel<<<NPIX / 64, 128, LN1_SMEM>>>(x, norm1_g, norm1_b, Xw);

    // 2. Sedenion GEMM + GELU + reverse-window scatter -> Z
    hgemm<4, 8><<<dim3(DWIN / 128, NWIN / 128), 256, SMEM>>>(
        Xw, wf, Z, NWIN, DWIN, DWIN, nullptr, nullptr);

    // 3. proj + bias + residual(x) -> X2 fp16, 96-wide tiles
    hgemm<1, 6><<<dim3(2, NPIX / 128), 256, SMEM>>>(
        Z, projH, X2, NPIX, Cc, Cc, proj_b, x);

    // 4. fc1 + LN2 fused -> U fp16   (131072 x 768 x 192)
    fc1_ln_fused<<<dim3(DH / 128, NPIX / 128), 256, FC1_SMEM>>>(
        X2, fc1H, U, norm2_g, norm2_b, fc1_b);

    // 5. fc2 + bias + residual(X2 fp16), transposed store -> out fp32
    hgemm<3, 6><<<dim3(2, NPIX / 128), 256, SMEM>>>(
        U, fc2H, out, NPIX, Cc, DH, fc2_b, X2);
}

// round 16
// speedup vs baseline: 1.0052x; 1.0052x over previous
#include <cuda_runtime.h>
#include <cuda_fp16.h>
#include <cstdint>
#include <math.h>

// ---------------- problem constants ----------------
#define Cc   192
#define HW   65536           // 256*256
#define NPIX 131072          // B*H*W
#define DWIN 3072            // 16*C
#define NWIN 8192            // B*(H/4)*(W/4)
#define DH   768             // 4*C

// ---------------- scratch (device globals: allocation-free) ----------------
__device__ __half g_wf [(size_t)DWIN * DWIN];      // 18.9 MB  ([K][N] row-major)
__device__ __half g_Xw [(size_t)NWIN * DWIN];      // 50.3 MB
__device__ __half g_xh [(size_t)NPIX * Cc];        // 50.3 MB (x, fp16 row-major)
__device__ __half g_Z  [(size_t)NPIX * Cc];        // 50.3 MB
__device__ __half g_X2 [(size_t)NPIX * Cc];        // 50.3 MB (residual chain: fp16)
__device__ __half g_T  [(size_t)NPIX * Cc];        // 50.3 MB
__device__ __half g_U  [(size_t)NPIX * DH];        // 201.3 MB
__device__ __half g_projH[Cc * Cc];
__device__ __half g_fc1H [Cc * DH];
__device__ __half g_fc2H [DH * Cc];

// ---------------- helpers ----------------
__device__ __forceinline__ float gelu_exact(float x) {
    return 0.5f * x * (1.0f + erff(x * 0.70710678118654752f));
}
__device__ __forceinline__ uint32_t smem_u32(const void* p) {
    uint32_t a;
    asm("{ .reg .u64 t; cvta.to.shared.u64 t, %1; cvt.u32.u64 %0, t; }" : "=r"(a) : "l"(p));
    return a;
}

__device__ __forceinline__ int cd_sign16(int i, int j) {
    int s = 1;
    for (int n = 16; n > 1;) {
        int h = n >> 1;
        if (i < h && j < h) {
        } else if (i < h) {
            int t = j - h; j = i; i = t;
        } else if (j < h) {
            if (j != 0) s = -s;
            i = i - h;
        } else {
            int ip = i - h, jp = j - h;
            if (jp == 0) s = -s;
            i = jp; j = ip;
        }
        n = h;
    }
    return s;
}

// ---------------- merged prep kernel -------------------------------------
#define WF_E4    (DWIN * (DWIN / 4))
#define WF_BLK   (WF_E4 / 256)
#define CV_PROJ4 (Cc * Cc / 4)
#define CV_FC14  (Cc * DH / 4)
#define CV_FC24  (DH * Cc / 4)
#define CV_TOT4  (CV_PROJ4 + CV_FC14 + CV_FC24)
#define CV_BLK   ((CV_TOT4 + 255) / 256)

__global__ void prep_kernel(const float* __restrict__ w_sed, __half* __restrict__ wf,
                            const float* __restrict__ proj_w, __half* __restrict__ projH,
                            const float* __restrict__ fc1_w,  __half* __restrict__ fc1H,
                            const float* __restrict__ fc2_w,  __half* __restrict__ fc2H) {
    int blk = blockIdx.x;
    if (blk < WF_BLK) {
        int e4 = blk * 256 + threadIdx.x;
        int row  = e4 / (DWIN / 4);
        int col4 = (e4 % (DWIN / 4)) * 4;
        int i = row / Cc, a = row % Cc;
        int k = col4 / Cc, b = col4 % Cc;
        int j = i ^ k;
        float s = (float)cd_sign16(i, j);
        float4 v = *(const float4*)(w_sed + ((size_t)j * Cc + a) * Cc + b);
        __half2* d = (__half2*)(wf + (size_t)row * DWIN + col4);
        d[0] = __floats2half2_rn(s * v.x, s * v.y);
        d[1] = __floats2half2_rn(s * v.z, s * v.w);
    } else {
        int e4 = (blk - WF_BLK) * 256 + threadIdx.x;
        const float* src; __half* dst;
        if (e4 < CV_PROJ4) {
            src = proj_w + e4 * 4; dst = projH + e4 * 4;
        } else if (e4 < CV_PROJ4 + CV_FC14) {
            int o = (e4 - CV_PROJ4) * 4; src = fc1_w + o; dst = fc1H + o;
        } else if (e4 < CV_TOT4) {
            int o = (e4 - CV_PROJ4 - CV_FC14) * 4; src = fc2_w + o; dst = fc2H + o;
        } else return;
        float4 v = *(const float4*)src;
        __half2* d = (__half2*)dst;
        d[0] = __floats2half2_rn(v.x, v.y);
        d[1] = __floats2half2_rn(v.z, v.w);
    }
}

// ---------------- kernel: LN1 via smem transpose + xh emit -----------------
// Also writes xh = x as fp16 row-major [NPIX][Cc] for the proj residual.
#define LN1_SMEM (192 * 68 * 4)   // 52224 bytes

__global__ __launch_bounds__(128)
void ln1_window_kernel(const float* __restrict__ x,
                       const float* __restrict__ g,
                       const float* __restrict__ be,
                       __half* __restrict__ Xw,
                       __half* __restrict__ xh) {
    extern __shared__ float s[];   // [192][68]
    int t  = threadIdx.x;
    int n0 = blockIdx.x * 64;
    int b  = n0 >> 16;
    int hw0 = n0 & (HW - 1);
    const float* xb = x + (size_t)b * Cc * HW + hw0;
#pragma unroll
    for (int j = 0; j < 24; j++) {
        int idx = t + j * 128;
        int c = idx >> 4, q = idx & 15;
        float4 v = *(const float4*)(xb + (size_t)c * HW + q * 4);
        float* d = &s[c * 68 + q * 4];
        d[0] = v.x; d[1] = v.y; d[2] = v.z; d[3] = v.w;
    }
    __syncthreads();
    if (t < 64) {
        int n  = n0 + t;
        int hw = n & (HW - 1);
        int h  = hw >> 8, w = hw & 255;
        float sum = 0.f, sum2 = 0.f;
#pragma unroll 4
        for (int c = 0; c < Cc; c++) {
            float v = s[c * 68 + t];
            sum += v; sum2 += v * v;
        }
        float m  = sum * (1.0f / Cc);
        float rs = rsqrtf(sum2 * (1.0f / Cc) - m * m + 1e-5f);
        int r = (b << 12) + ((h >> 2) << 6) + (w >> 2);
        int p = ((h & 3) << 2) + (w & 3);
        __half* dst = Xw + (size_t)r * DWIN + p * Cc;
        __half* xd  = xh + (size_t)n * Cc;
#pragma unroll
        for (int c8 = 0; c8 < Cc; c8 += 8) {
            __half2 h4[4], x4[4];
#pragma unroll
            for (int u = 0; u < 4; u++) {
                int c = c8 + u * 2;
                float r0 = s[(c + 0) * 68 + t];
                float r1 = s[(c + 1) * 68 + t];
                x4[u] = __floats2half2_rn(r0, r1);
                h4[u] = __floats2half2_rn((r0 - m) * rs * g[c + 0] + be[c + 0],
                                          (r1 - m) * rs * g[c + 1] + be[c + 1]);
            }
            *(uint4*)(dst + c8) = *(uint4*)h4;
            *(uint4*)(xd + c8)  = *(uint4*)x4;
        }
    }
}

// ---------------- kernel: LN2, one warp per row (fp16 in, fp16 out) --------
__global__ void ln2_kernel(const __half* __restrict__ X2,
                           const float* __restrict__ g,
                           const float* __restrict__ be,
                           __half* __restrict__ T) {
    int gt   = blockIdx.x * blockDim.x + threadIdx.x;
    int row  = gt >> 5;
    int lane = gt & 31;
    if (row >= NPIX) return;
    const __half* src = X2 + (size_t)row * Cc;
    float vals[6];
    float s = 0.f, s2 = 0.f;
#pragma unroll
    for (int i = 0; i < 3; i++) {
        __half2 hv = *(const __half2*)(src + lane * 2 + i * 64);
        float2 f = __half22float2(hv);
        vals[i * 2] = f.x; vals[i * 2 + 1] = f.y;
        s += f.x + f.y; s2 += f.x * f.x + f.y * f.y;
    }
#pragma unroll
    for (int o = 16; o > 0; o >>= 1) {
        s  += __shfl_xor_sync(0xffffffffu, s,  o);
        s2 += __shfl_xor_sync(0xffffffffu, s2, o);
    }
    float m  = s * (1.0f / Cc);
    float rs = rsqrtf(s2 * (1.0f / Cc) - m * m + 1e-5f);
    __half* dst = T + (size_t)row * Cc;
#pragma unroll
    for (int i = 0; i < 3; i++) {
        int c = lane * 2 + i * 64;
        float v0 = (vals[i * 2]     - m) * rs * g[c]     + be[c];
        float v1 = (vals[i * 2 + 1] - m) * rs * g[c + 1] + be[c + 1];
        *(__half2*)(dst + c) = __floats2half2_rn(v0, v1);
    }
}

// ---------------- fp16 mma.sync GEMM, 3-stage cp.async, 2 CTAs/SM -----------
// MODE 1: X2(fp16) = D + bias + res_rowmaj(fp16)      (proj + residual xh)
// MODE 2: C(fp16)  = gelu(D + bias)                   (fc1)
// MODE 3: out_bchw(fp32) = res_rowmaj(fp16) + D + b   (fc2, transposed store)
// MODE 4: Z(fp16)  = gelu(D), reverse-window scatter  (GEMM1 fused)
#define STG 32768

__device__ __forceinline__ void hmma(float* c, const uint32_t* a, const uint32_t* b) {
    asm volatile(
        "mma.sync.aligned.m16n8k16.row.col.f32.f16.f16.f32 "
        "{%0,%1,%2,%3}, {%4,%5,%6,%7}, {%8,%9}, {%0,%1,%2,%3};"
        : "+f"(c[0]), "+f"(c[1]), "+f"(c[2]), "+f"(c[3])
        : "r"(a[0]), "r"(a[1]), "r"(a[2]), "r"(a[3]), "r"(b[0]), "r"(b[1]));
}

template <int MODE, int NT>
__global__ __launch_bounds__(256, 2)
void hgemm(const __half* __restrict__ A, const __half* __restrict__ Bm,
           void* __restrict__ Cv, int M, int N, int K,
           const float* __restrict__ bias, const void* __restrict__ res) {
    extern __shared__ char smem[];
    uint32_t sb = smem_u32(smem);

    int tid  = threadIdx.x;
    int wid  = tid >> 5, lane = tid & 31;
    int wm   = wid & 3;
    int wn   = wid >> 2;
    int row0 = blockIdx.y * 128;
    int col0 = blockIdx.x * (NT * 16);
    int lg   = lane >> 2;
    int lt   = lane & 3;

    float cacc[2][NT][4];
#pragma unroll
    for (int mt = 0; mt < 2; mt++)
#pragma unroll
        for (int nt = 0; nt < NT; nt++)
#pragma unroll
            for (int q = 0; q < 4; q++) cacc[mt][nt][q] = 0.f;

    int nk = K >> 6;

    auto load_stage = [&](int kt, int buf) {
        uint32_t sA = sb + buf * STG;
        uint32_t sB = sA + 16384;
#pragma unroll
        for (int i = 0; i < 4; i++) {
            int idx = tid + i * 256;
            int m = idx >> 3, c = idx & 7;
            const __half* src = A + (size_t)(row0 + m) * K + (kt << 6) + (c << 3);
            uint32_t dst = sA + m * 128 + ((c ^ (m & 7)) << 4);
            asm volatile("cp.async.cg.shared.global [%0], [%1], 16;"
                         :: "r"(dst), "l"(src) : "memory");
        }
#pragma unroll
        for (int i = 0; i < NT / 2; i++) {
            int idx = tid + i * 256;
            int k = idx / (2 * NT), c = idx % (2 * NT);
            int n = col0 + (c << 3);
            const __half* src = Bm + (size_t)((kt << 6) + k) * N + (n < N ? n : 0);
            uint32_t dst = sB + k * 256 + (((c & 8) | ((c & 7) ^ (k & 7))) << 4);
            int ssz = (n < N) ? 16 : 0;
            asm volatile("cp.async.cg.shared.global [%0], [%1], 16, %2;"
                         :: "r"(dst), "l"(src), "r"(ssz) : "memory");
        }
        asm volatile("cp.async.commit_group;" ::: "memory");
    };

    uint32_t af[2][2][4], bf[2][NT][2];
    auto load_frags = [&](uint32_t sA, uint32_t sB, int ks, int pb) {
#pragma unroll
        for (int mt = 0; mt < 2; mt++) {
            int m = wm * 32 + mt * 16 + (lane & 15);
            int c = ks * 2 + (lane >> 4);
            uint32_t addr = sA + m * 128 + ((c ^ (m & 7)) << 4);
            asm volatile("ldmatrix.sync.aligned.m8n8.x4.shared.b16 {%0,%1,%2,%3}, [%4];"
                         : "=r"(af[pb][mt][0]), "=r"(af[pb][mt][1]),
                           "=r"(af[pb][mt][2]), "=r"(af[pb][mt][3])
                         : "r"(addr));
        }
#pragma unroll
        for (int np = 0; np < NT / 2; np++) {
            int k  = ks * 16 + (lane & 15);
            int cn = wn * NT + np * 2 + (lane >> 4);
            uint32_t addr = sB + k * 256 + (((cn & 8) | ((cn & 7) ^ (k & 7))) << 4);
            asm volatile("ldmatrix.sync.aligned.m8n8.x4.trans.shared.b16 {%0,%1,%2,%3}, [%4];"
                         : "=r"(bf[pb][np * 2][0]), "=r"(bf[pb][np * 2][1]),
                           "=r"(bf[pb][np * 2 + 1][0]), "=r"(bf[pb][np * 2 + 1][1])
                         : "r"(addr));
        }
    };

    load_stage(0, 0);
    if (nk > 1) load_stage(1, 1);

    for (int kt = 0; kt < nk; kt++) {
        int buf = kt % 3;
        if (kt + 1 < nk) {
            asm volatile("cp.async.wait_group 1;" ::: "memory");
        } else {
            asm volatile("cp.async.wait_group 0;" ::: "memory");
        }
        __syncthreads();
        if (kt + 2 < nk) load_stage(kt + 2, (kt + 2) % 3);

        uint32_t sA = sb + buf * STG;
        uint32_t sB = sA + 16384;

        load_frags(sA, sB, 0, 0);
#pragma unroll
        for (int ks = 0; ks < 4; ks++) {
            int cur = ks & 1;
            if (ks < 3) load_frags(sA, sB, ks + 1, cur ^ 1);
#pragma unroll
            for (int mt = 0; mt < 2; mt++)
#pragma unroll
                for (int nt = 0; nt < NT; nt++)
                    hmma(cacc[mt][nt], af[cur][mt], bf[cur][nt]);
        }
    }
    __syncthreads();

    // ---------------- epilogue ----------------
#pragma unroll
    for (int mt = 0; mt < 2; mt++) {
#pragma unroll
        for (int nt = 0; nt < NT; nt++) {
            int r = row0 + wm * 32 + mt * 16 + lg;
            int c = col0 + wn * (NT * 8) + nt * 8 + lt * 2;
            if (c >= N) continue;
#pragma unroll
            for (int half = 0; half < 2; half++) {
                int rr = r + half * 8;
                float v0 = cacc[mt][nt][half * 2 + 0];
                float v1 = cacc[mt][nt][half * 2 + 1];
                if (MODE == 1) {
                    const __half* rp = (const __half*)res + (size_t)rr * Cc;
                    float2 rf = __half22float2(*(const __half2*)(rp + c));
                    float o0 = v0 + bias[c]     + rf.x;
                    float o1 = v1 + bias[c + 1] + rf.y;
                    *(__half2*)((__half*)Cv + (size_t)rr * N + c) = __floats2half2_rn(o0, o1);
                } else if (MODE == 2) {
                    *(__half2*)((__half*)Cv + (size_t)rr * N + c) =
                        __floats2half2_rn(gelu_exact(v0 + bias[c]),
                                          gelu_exact(v1 + bias[c + 1]));
                } else if (MODE == 3) {
                    int rb = rr >> 16, rhw = rr & (HW - 1);
                    const __half* rp = (const __half*)res + (size_t)rr * Cc;
                    float* op = (float*)Cv + (size_t)rb * Cc * HW + rhw;
                    float2 rf = __half22float2(*(const __half2*)(rp + c));
                    op[(size_t)c * HW]       = rf.x + v0 + bias[c];
                    op[(size_t)(c + 1) * HW] = rf.y + v1 + bias[c + 1];
                } else {  // MODE 4
                    int p  = c / Cc;
                    int cc = c - p * Cc;
                    int bb = rr >> 12;
                    int hq = (rr >> 6) & 63, wq = rr & 63;
                    int h = (hq << 2) + (p >> 2), w = (wq << 2) + (p & 3);
                    int n = (bb << 16) + (h << 8) + w;
                    *(__half2*)((__half*)Cv + (size_t)n * Cc + cc) =
                        __floats2half2_rn(gelu_exact(v0), gelu_exact(v1));
                }
            }
        }
    }
}

// ---------------- launch ----------------
extern "C" void kernel_launch(void* const* d_in, const int* in_sizes, int n_in,
                              void* d_out, int out_size) {
    const float* x       = (const float*)d_in[0];
    const float* norm1_g = (const float*)d_in[1];
    const float* norm1_b = (const float*)d_in[2];
    const float* w_sed   = (const float*)d_in[3];
    const float* proj_w  = (const float*)d_in[4];
    const float* proj_b  = (const float*)d_in[5];
    const float* norm2_g = (const float*)d_in[6];
    const float* norm2_b = (const float*)d_in[7];
    const float* fc1_w   = (const float*)d_in[8];
    const float* fc1_b   = (const float*)d_in[9];
    const float* fc2_w   = (const float*)d_in[10];
    const float* fc2_b   = (const float*)d_in[11];
    float* out = (float*)d_out;

    __half *wf, *Xw, *xh, *Z, *X2, *T, *U, *projH, *fc1H, *fc2H;
    cudaGetSymbolAddress((void**)&wf,    g_wf);
    cudaGetSymbolAddress((void**)&Xw,    g_Xw);
    cudaGetSymbolAddress((void**)&xh,    g_xh);
    cudaGetSymbolAddress((void**)&Z,     g_Z);
    cudaGetSymbolAddress((void**)&X2,    g_X2);
    cudaGetSymbolAddress((void**)&T,     g_T);
    cudaGetSymbolAddress((void**)&U,     g_U);
    cudaGetSymbolAddress((void**)&projH, g_projH);
    cudaGetSymbolAddress((void**)&fc1H,  g_fc1H);
    cudaGetSymbolAddress((void**)&fc2H,  g_fc2H);

    const int SMEM = 3 * STG;  // 98304
    cudaFuncSetAttribute((hgemm<1, 6>), cudaFuncAttributeMaxDynamicSharedMemorySize, SMEM);
    cudaFuncSetAttribute((hgemm<2, 8>), cudaFuncAttributeMaxDynamicSharedMemorySize, SMEM);
    cudaFuncSetAttribute((hgemm<3, 6>), cudaFuncAttributeMaxDynamicSharedMemorySize, SMEM);
    cudaFuncSetAttribute((hgemm<4, 8>), cudaFuncAttributeMaxDynamicSharedMemorySize, SMEM);
    cudaFuncSetAttribute(ln1_window_kernel, cudaFuncAttributeMaxDynamicSharedMemorySize, LN1_SMEM);

    // 0. merged prep: wf build + all weight fp16 conversions (one launch)
    prep_kernel<<<WF_BLK + CV_BLK, 256>>>(w_sed, wf, proj_w, projH,
                                          fc1_w, fc1H, fc2_w, fc2H);

    // 1. LN1 + window partition + xh emit (coalesced x reads)
    ln1_window_kernel<<<NPIX / 64, 128, LN1_SMEM>>>(x, norm1_g, norm1_b, Xw, xh);

    // 2. Sedenion GEMM + GELU + reverse-window scatter -> Z
    hgemm<4, 8><<<dim3(DWIN / 128, NWIN / 128), 256, SMEM>>>(
        Xw, wf, Z, NWIN, DWIN, DWIN, nullptr, nullptr);

    // 3. proj + bias + residual(xh fp16 rowmajor) -> X2 fp16, 96-wide tiles
    hgemm<1, 6><<<dim3(2, NPIX / 128), 256, SMEM>>>(
        Z, projH, X2, NPIX, Cc, Cc, proj_b, xh);

    // 4. LN2 -> T (fp16 in/out)
    ln2_kernel<<<(NPIX * 32 + 255) / 256, 256>>>(X2, norm2_g, norm2_b, T);

    // 5. fc1 + bias + GELU -> U fp16   (131072 x 768 x 192)
    hgemm<2, 8><<<dim3(DH / 128, NPIX / 128), 256, SMEM>>>(
        T, fc1H, U, NPIX, DH, Cc, fc1_b, nullptr);

    // 6. fc2 + bias + residual(X2 fp16), transposed store -> out fp32
    hgemm<3, 6><<<dim3(2, NPIX / 128), 256, SMEM>>>(
        U, fc2H, out, NPIX, Cc, DH, fc2_b, X2);
}

// round 17
// speedup vs baseline: 1.0139x; 1.0086x over previous
#include <cuda_runtime.h>
#include <cuda_fp16.h>
#include <cstdint>
#include <math.h>

// ---------------- problem constants ----------------
#define Cc   192
#define HW   65536           // 256*256
#define NPIX 131072          // B*H*W
#define DWIN 3072            // 16*C
#define NWIN 8192            // B*(H/4)*(W/4)
#define DH   768             // 4*C

// ---------------- scratch (device globals: allocation-free) ----------------
__device__ __half g_wf [(size_t)DWIN * DWIN];      // 18.9 MB  ([K][N] row-major)
__device__ __half g_Xw [(size_t)NWIN * DWIN];      // 50.3 MB
__device__ __half g_xh [(size_t)NPIX * Cc];        // 50.3 MB (x, fp16 row-major)
__device__ __half g_Z  [(size_t)NPIX * Cc];        // 50.3 MB
__device__ __half g_X2 [(size_t)NPIX * Cc];        // 50.3 MB (residual chain: fp16)
__device__ __half g_T  [(size_t)NPIX * Cc];        // 50.3 MB
__device__ __half g_U  [(size_t)NPIX * DH];        // 201.3 MB
__device__ __half g_projH[Cc * Cc];
__device__ __half g_fc1H [Cc * DH];
__device__ __half g_fc2H [DH * Cc];

// ---------------- helpers ----------------
__device__ __forceinline__ float gelu_exact(float x) {
    return 0.5f * x * (1.0f + erff(x * 0.70710678118654752f));
}
__device__ __forceinline__ uint32_t smem_u32(const void* p) {
    uint32_t a;
    asm("{ .reg .u64 t; cvta.to.shared.u64 t, %1; cvt.u32.u64 %0, t; }" : "=r"(a) : "l"(p));
    return a;
}

__device__ __forceinline__ int cd_sign16(int i, int j) {
    int s = 1;
    for (int n = 16; n > 1;) {
        int h = n >> 1;
        if (i < h && j < h) {
        } else if (i < h) {
            int t = j - h; j = i; i = t;
        } else if (j < h) {
            if (j != 0) s = -s;
            i = i - h;
        } else {
            int ip = i - h, jp = j - h;
            if (jp == 0) s = -s;
            i = jp; j = ip;
        }
        n = h;
    }
    return s;
}

// ---------------- merged prep kernel -------------------------------------
#define WF_E4    (DWIN * (DWIN / 4))
#define WF_BLK   (WF_E4 / 256)
#define CV_PROJ4 (Cc * Cc / 4)
#define CV_FC14  (Cc * DH / 4)
#define CV_FC24  (DH * Cc / 4)
#define CV_TOT4  (CV_PROJ4 + CV_FC14 + CV_FC24)
#define CV_BLK   ((CV_TOT4 + 255) / 256)

__global__ void prep_kernel(const float* __restrict__ w_sed, __half* __restrict__ wf,
                            const float* __restrict__ proj_w, __half* __restrict__ projH,
                            const float* __restrict__ fc1_w,  __half* __restrict__ fc1H,
                            const float* __restrict__ fc2_w,  __half* __restrict__ fc2H) {
    int blk = blockIdx.x;
    if (blk < WF_BLK) {
        int e4 = blk * 256 + threadIdx.x;
        int row  = e4 / (DWIN / 4);
        int col4 = (e4 % (DWIN / 4)) * 4;
        int i = row / Cc, a = row % Cc;
        int k = col4 / Cc, b = col4 % Cc;
        int j = i ^ k;
        float s = (float)cd_sign16(i, j);
        float4 v = *(const float4*)(w_sed + ((size_t)j * Cc + a) * Cc + b);
        __half2* d = (__half2*)(wf + (size_t)row * DWIN + col4);
        d[0] = __floats2half2_rn(s * v.x, s * v.y);
        d[1] = __floats2half2_rn(s * v.z, s * v.w);
    } else {
        int e4 = (blk - WF_BLK) * 256 + threadIdx.x;
        const float* src; __half* dst;
        if (e4 < CV_PROJ4) {
            src = proj_w + e4 * 4; dst = projH + e4 * 4;
        } else if (e4 < CV_PROJ4 + CV_FC14) {
            int o = (e4 - CV_PROJ4) * 4; src = fc1_w + o; dst = fc1H + o;
        } else if (e4 < CV_TOT4) {
            int o = (e4 - CV_PROJ4 - CV_FC14) * 4; src = fc2_w + o; dst = fc2H + o;
        } else return;
        float4 v = *(const float4*)src;
        __half2* d = (__half2*)dst;
        d[0] = __floats2half2_rn(v.x, v.y);
        d[1] = __floats2half2_rn(v.z, v.w);
    }
}

// ---------------- kernel: LN1 via smem transpose + xh emit -----------------
// Phase 2a: threads 0..63 compute per-pixel stats -> smem.
// Phase 2b: all 128 threads write (pixel = t&63, channel half = (t>>6)*96).
#define LN1_SMEM (192 * 68 * 4)   // 52224 bytes

__global__ __launch_bounds__(128)
void ln1_window_kernel(const float* __restrict__ x,
                       const float* __restrict__ g,
                       const float* __restrict__ be,
                       __half* __restrict__ Xw,
                       __half* __restrict__ xh) {
    extern __shared__ float s[];   // [192][68]
    __shared__ float sm[64], sr[64];
    int t  = threadIdx.x;
    int n0 = blockIdx.x * 64;
    int b  = n0 >> 16;
    int hw0 = n0 & (HW - 1);
    const float* xb = x + (size_t)b * Cc * HW + hw0;
#pragma unroll
    for (int j = 0; j < 24; j++) {
        int idx = t + j * 128;
        int c = idx >> 4, q = idx & 15;
        float4 v = *(const float4*)(xb + (size_t)c * HW + q * 4);
        float* d = &s[c * 68 + q * 4];
        d[0] = v.x; d[1] = v.y; d[2] = v.z; d[3] = v.w;
    }
    __syncthreads();
    if (t < 64) {
        float sum = 0.f, sum2 = 0.f;
#pragma unroll 4
        for (int c = 0; c < Cc; c++) {
            float v = s[c * 68 + t];
            sum += v; sum2 += v * v;
        }
        float m = sum * (1.0f / Cc);
        sm[t] = m;
        sr[t] = rsqrtf(sum2 * (1.0f / Cc) - m * m + 1e-5f);
    }
    __syncthreads();
    {
        int pl = t & 63;           // pixel within block
        int c0 = (t >> 6) * 96;    // channel half
        float m  = sm[pl];
        float rs = sr[pl];
        int n  = n0 + pl;
        int hw = n & (HW - 1);
        int h  = hw >> 8, w = hw & 255;
        int r = (b << 12) + ((h >> 2) << 6) + (w >> 2);
        int p = ((h & 3) << 2) + (w & 3);
        __half* dst = Xw + (size_t)r * DWIN + p * Cc;
        __half* xd  = xh + (size_t)n * Cc;
#pragma unroll
        for (int c8 = c0; c8 < c0 + 96; c8 += 8) {
            __half2 h4[4], x4[4];
#pragma unroll
            for (int u = 0; u < 4; u++) {
                int c = c8 + u * 2;
                float r0 = s[(c + 0) * 68 + pl];
                float r1 = s[(c + 1) * 68 + pl];
                x4[u] = __floats2half2_rn(r0, r1);
                h4[u] = __floats2half2_rn((r0 - m) * rs * g[c + 0] + be[c + 0],
                                          (r1 - m) * rs * g[c + 1] + be[c + 1]);
            }
            *(uint4*)(dst + c8) = *(uint4*)h4;
            *(uint4*)(xd + c8)  = *(uint4*)x4;
        }
    }
}

// ---------------- kernel: LN2, one warp per row (fp16 in, fp16 out) --------
__global__ void ln2_kernel(const __half* __restrict__ X2,
                           const float* __restrict__ g,
                           const float* __restrict__ be,
                           __half* __restrict__ T) {
    int gt   = blockIdx.x * blockDim.x + threadIdx.x;
    int row  = gt >> 5;
    int lane = gt & 31;
    if (row >= NPIX) return;
    const __half* src = X2 + (size_t)row * Cc;
    float vals[6];
    float s = 0.f, s2 = 0.f;
#pragma unroll
    for (int i = 0; i < 3; i++) {
        __half2 hv = *(const __half2*)(src + lane * 2 + i * 64);
        float2 f = __half22float2(hv);
        vals[i * 2] = f.x; vals[i * 2 + 1] = f.y;
        s += f.x + f.y; s2 += f.x * f.x + f.y * f.y;
    }
#pragma unroll
    for (int o = 16; o > 0; o >>= 1) {
        s  += __shfl_xor_sync(0xffffffffu, s,  o);
        s2 += __shfl_xor_sync(0xffffffffu, s2, o);
    }
    float m  = s * (1.0f / Cc);
    float rs = rsqrtf(s2 * (1.0f / Cc) - m * m + 1e-5f);
    __half* dst = T + (size_t)row * Cc;
#pragma unroll
    for (int i = 0; i < 3; i++) {
        int c = lane * 2 + i * 64;
        float v0 = (vals[i * 2]     - m) * rs * g[c]     + be[c];
        float v1 = (vals[i * 2 + 1] - m) * rs * g[c + 1] + be[c + 1];
        *(__half2*)(dst + c) = __floats2half2_rn(v0, v1);
    }
}

// ---------------- fp16 mma.sync GEMM, 3-stage cp.async, 2 CTAs/SM -----------
// MODE 1: X2(fp16) = D + bias + res_rowmaj(fp16)      (proj + residual xh)
// MODE 2: C(fp16)  = gelu(D + bias)                   (fc1)
// MODE 3: out_bchw(fp32) = res_rowmaj(fp16) + D + b   (fc2, transposed store)
// MODE 4: Z(fp16)  = gelu(D), reverse-window scatter  (GEMM1 fused)
#define STG 32768

__device__ __forceinline__ void hmma(float* c, const uint32_t* a, const uint32_t* b) {
    asm volatile(
        "mma.sync.aligned.m16n8k16.row.col.f32.f16.f16.f32 "
        "{%0,%1,%2,%3}, {%4,%5,%6,%7}, {%8,%9}, {%0,%1,%2,%3};"
        : "+f"(c[0]), "+f"(c[1]), "+f"(c[2]), "+f"(c[3])
        : "r"(a[0]), "r"(a[1]), "r"(a[2]), "r"(a[3]), "r"(b[0]), "r"(b[1]));
}

template <int MODE, int NT>
__global__ __launch_bounds__(256, 2)
void hgemm(const __half* __restrict__ A, const __half* __restrict__ Bm,
           void* __restrict__ Cv, int M, int N, int K,
           const float* __restrict__ bias, const void* __restrict__ res) {
    extern __shared__ char smem[];
    uint32_t sb = smem_u32(smem);

    int tid  = threadIdx.x;
    int wid  = tid >> 5, lane = tid & 31;
    int wm   = wid & 3;
    int wn   = wid >> 2;
    int row0 = blockIdx.y * 128;
    int col0 = blockIdx.x * (NT * 16);
    int lg   = lane >> 2;
    int lt   = lane & 3;

    float cacc[2][NT][4];
#pragma unroll
    for (int mt = 0; mt < 2; mt++)
#pragma unroll
        for (int nt = 0; nt < NT; nt++)
#pragma unroll
            for (int q = 0; q < 4; q++) cacc[mt][nt][q] = 0.f;

    int nk = K >> 6;

    auto load_stage = [&](int kt, int buf) {
        uint32_t sA = sb + buf * STG;
        uint32_t sB = sA + 16384;
#pragma unroll
        for (int i = 0; i < 4; i++) {
            int idx = tid + i * 256;
            int m = idx >> 3, c = idx & 7;
            const __half* src = A + (size_t)(row0 + m) * K + (kt << 6) + (c << 3);
            uint32_t dst = sA + m * 128 + ((c ^ (m & 7)) << 4);
            asm volatile("cp.async.cg.shared.global [%0], [%1], 16;"
                         :: "r"(dst), "l"(src) : "memory");
        }
#pragma unroll
        for (int i = 0; i < NT / 2; i++) {
            int idx = tid + i * 256;
            int k = idx / (2 * NT), c = idx % (2 * NT);
            int n = col0 + (c << 3);
            const __half* src = Bm + (size_t)((kt << 6) + k) * N + (n < N ? n : 0);
            uint32_t dst = sB + k * 256 + (((c & 8) | ((c & 7) ^ (k & 7))) << 4);
            int ssz = (n < N) ? 16 : 0;
            asm volatile("cp.async.cg.shared.global [%0], [%1], 16, %2;"
                         :: "r"(dst), "l"(src), "r"(ssz) : "memory");
        }
        asm volatile("cp.async.commit_group;" ::: "memory");
    };

    uint32_t af[2][2][4], bf[2][NT][2];
    auto load_frags = [&](uint32_t sA, uint32_t sB, int ks, int pb) {
#pragma unroll
        for (int mt = 0; mt < 2; mt++) {
            int m = wm * 32 + mt * 16 + (lane & 15);
            int c = ks * 2 + (lane >> 4);
            uint32_t addr = sA + m * 128 + ((c ^ (m & 7)) << 4);
            asm volatile("ldmatrix.sync.aligned.m8n8.x4.shared.b16 {%0,%1,%2,%3}, [%4];"
                         : "=r"(af[pb][mt][0]), "=r"(af[pb][mt][1]),
                           "=r"(af[pb][mt][2]), "=r"(af[pb][mt][3])
                         : "r"(addr));
        }
#pragma unroll
        for (int np = 0; np < NT / 2; np++) {
            int k  = ks * 16 + (lane & 15);
            int cn = wn * NT + np * 2 + (lane >> 4);
            uint32_t addr = sB + k * 256 + (((cn & 8) | ((cn & 7) ^ (k & 7))) << 4);
            asm volatile("ldmatrix.sync.aligned.m8n8.x4.trans.shared.b16 {%0,%1,%2,%3}, [%4];"
                         : "=r"(bf[pb][np * 2][0]), "=r"(bf[pb][np * 2][1]),
                           "=r"(bf[pb][np * 2 + 1][0]), "=r"(bf[pb][np * 2 + 1][1])
                         : "r"(addr));
        }
    };

    load_stage(0, 0);
    if (nk > 1) load_stage(1, 1);

    for (int kt = 0; kt < nk; kt++) {
        int buf = kt % 3;
        if (kt + 1 < nk) {
            asm volatile("cp.async.wait_group 1;" ::: "memory");
        } else {
            asm volatile("cp.async.wait_group 0;" ::: "memory");
        }
        __syncthreads();
        if (kt + 2 < nk) load_stage(kt + 2, (kt + 2) % 3);

        uint32_t sA = sb + buf * STG;
        uint32_t sB = sA + 16384;

        load_frags(sA, sB, 0, 0);
#pragma unroll
        for (int ks = 0; ks < 4; ks++) {
            int cur = ks & 1;
            if (ks < 3) load_frags(sA, sB, ks + 1, cur ^ 1);
#pragma unroll
            for (int mt = 0; mt < 2; mt++)
#pragma unroll
                for (int nt = 0; nt < NT; nt++)
                    hmma(cacc[mt][nt], af[cur][mt], bf[cur][nt]);
        }
    }
    __syncthreads();

    // ---------------- epilogue ----------------
#pragma unroll
    for (int mt = 0; mt < 2; mt++) {
#pragma unroll
        for (int nt = 0; nt < NT; nt++) {
            int r = row0 + wm * 32 + mt * 16 + lg;
            int c = col0 + wn * (NT * 8) + nt * 8 + lt * 2;
            if (c >= N) continue;
#pragma unroll
            for (int half = 0; half < 2; half++) {
                int rr = r + half * 8;
                float v0 = cacc[mt][nt][half * 2 + 0];
                float v1 = cacc[mt][nt][half * 2 + 1];
                if (MODE == 1) {
                    const __half* rp = (const __half*)res + (size_t)rr * Cc;
                    float2 rf = __half22float2(*(const __half2*)(rp + c));
                    float o0 = v0 + bias[c]     + rf.x;
                    float o1 = v1 + bias[c + 1] + rf.y;
                    *(__half2*)((__half*)Cv + (size_t)rr * N + c) = __floats2half2_rn(o0, o1);
                } else if (MODE == 2) {
                    *(__half2*)((__half*)Cv + (size_t)rr * N + c) =
                        __floats2half2_rn(gelu_exact(v0 + bias[c]),
                                          gelu_exact(v1 + bias[c + 1]));
                } else if (MODE == 3) {
                    int rb = rr >> 16, rhw = rr & (HW - 1);
                    const __half* rp = (const __half*)res + (size_t)rr * Cc;
                    float* op = (float*)Cv + (size_t)rb * Cc * HW + rhw;
                    float2 rf = __half22float2(*(const __half2*)(rp + c));
                    op[(size_t)c * HW]       = rf.x + v0 + bias[c];
                    op[(size_t)(c + 1) * HW] = rf.y + v1 + bias[c + 1];
                } else {  // MODE 4
                    int p  = c / Cc;
                    int cc = c - p * Cc;
                    int bb = rr >> 12;
                    int hq = (rr >> 6) & 63, wq = rr & 63;
                    int h = (hq << 2) + (p >> 2), w = (wq << 2) + (p & 3);
                    int n = (bb << 16) + (h << 8) + w;
                    *(__half2*)((__half*)Cv + (size_t)n * Cc + cc) =
                        __floats2half2_rn(gelu_exact(v0), gelu_exact(v1));
                }
            }
        }
    }
}

// ---------------- launch ----------------
extern "C" void kernel_launch(void* const* d_in, const int* in_sizes, int n_in,
                              void* d_out, int out_size) {
    const float* x       = (const float*)d_in[0];
    const float* norm1_g = (const float*)d_in[1];
    const float* norm1_b = (const float*)d_in[2];
    const float* w_sed   = (const float*)d_in[3];
    const float* proj_w  = (const float*)d_in[4];
    const float* proj_b  = (const float*)d_in[5];
    const float* norm2_g = (const float*)d_in[6];
    const float* norm2_b = (const float*)d_in[7];
    const float* fc1_w   = (const float*)d_in[8];
    const float* fc1_b   = (const float*)d_in[9];
    const float* fc2_w   = (const float*)d_in[10];
    const float* fc2_b   = (const float*)d_in[11];
    float* out = (float*)d_out;

    __half *wf, *Xw, *xh, *Z, *X2, *T, *U, *projH, *fc1H, *fc2H;
    cudaGetSymbolAddress((void**)&wf,    g_wf);
    cudaGetSymbolAddress((void**)&Xw,    g_Xw);
    cudaGetSymbolAddress((void**)&xh,    g_xh);
    cudaGetSymbolAddress((void**)&Z,     g_Z);
    cudaGetSymbolAddress((void**)&X2,    g_X2);
    cudaGetSymbolAddress((void**)&T,     g_T);
    cudaGetSymbolAddress((void**)&U,     g_U);
    cudaGetSymbolAddress((void**)&projH, g_projH);
    cudaGetSymbolAddress((void**)&fc1H,  g_fc1H);
    cudaGetSymbolAddress((void**)&fc2H,  g_fc2H);

    const int SMEM = 3 * STG;  // 98304
    cudaFuncSetAttribute((hgemm<1, 6>), cudaFuncAttributeMaxDynamicSharedMemorySize, SMEM);
    cudaFuncSetAttribute((hgemm<2, 8>), cudaFuncAttributeMaxDynamicSharedMemorySize, SMEM);
    cudaFuncSetAttribute((hgemm<3, 6>), cudaFuncAttributeMaxDynamicSharedMemorySize, SMEM);
    cudaFuncSetAttribute((hgemm<4, 8>), cudaFuncAttributeMaxDynamicSharedMemorySize, SMEM);
    cudaFuncSetAttribute(ln1_window_kernel, cudaFuncAttributeMaxDynamicSharedMemorySize, LN1_SMEM);

    // 0. merged prep: wf build + all weight fp16 conversions (one launch)
    prep_kernel<<<WF_BLK + CV_BLK, 256>>>(w_sed, wf, proj_w, projH,
                                          fc1_w, fc1H, fc2_w, fc2H);

    // 1. LN1 + window partition + xh emit (coalesced x reads, 2-phase stores)
    ln1_window_kernel<<<NPIX / 64, 128, LN1_SMEM>>>(x, norm1_g, norm1_b, Xw, xh);

    // 2. Sedenion GEMM + GELU + reverse-window scatter -> Z
    hgemm<4, 8><<<dim3(DWIN / 128, NWIN / 128), 256, SMEM>>>(
        Xw, wf, Z, NWIN, DWIN, DWIN, nullptr, nullptr);

    // 3. proj + bias + residual(xh fp16 rowmajor) -> X2 fp16, 96-wide tiles
    hgemm<1, 6><<<dim3(2, NPIX / 128), 256, SMEM>>>(
        Z, projH, X2, NPIX, Cc, Cc, proj_b, xh);

    // 4. LN2 -> T (fp16 in/out)
    ln2_kernel<<<(NPIX * 32 + 255) / 256, 256>>>(X2, norm2_g, norm2_b, T);

    // 5. fc1 + bias + GELU -> U fp16   (131072 x 768 x 192)
    hgemm<2, 8><<<dim3(DH / 128, NPIX / 128), 256, SMEM>>>(
        T, fc1H, U, NPIX, DH, Cc, fc1_b, nullptr);

    // 6. fc2 + bias + residual(X2 fp16), transposed store -> out fp32
    hgemm<3, 6><<<dim3(2, NPIX / 128), 256, SMEM>>>(
        U, fc2H, out, NPIX, Cc, DH, fc2_b, X2);
}